// round 4
// baseline (speedup 1.0000x reference)
#include <cuda_runtime.h>
#include <stdint.h>

// Resolutions: floor(16 * growth^i) replicating numpy's float64 pipeline.
// Level 15: 16*growth^15 lands just below 4096 in float64 -> floor = 4095.
__constant__ float c_res[16] = {
    16.f, 23.f, 33.f, 48.f, 70.f, 101.f, 147.f, 212.f,
    307.f, 445.f, 645.f, 933.f, 1351.f, 1955.f, 2830.f, 4095.f
};

#define HG_P2 2654435761u
#define HG_P3 805459861u
#define HG_MASK 0x7FFFFu   // T-1, T = 2^19

// Dense smem grids for coarse levels (points in [0,1): ix+1 <= res).
#define L0_SIDE 17
#define L0_N    (17*17*17)     // 4913
#define L1_SIDE 24
#define L1_N    (24*24*24)     // 13824
#define SMEM_ENTRIES (L0_N + L1_N)              // 18737 float2
#define SMEM_BYTES   (SMEM_ENTRIES * 8)         // 149896 B < 227KB

__global__ __launch_bounds__(1024, 1) void hashgrid_kernel(
    const float* __restrict__ x,
    const float* __restrict__ table,
    float2* __restrict__ out,
    int n_points)
{
    extern __shared__ float2 sm[];

    // ---- Preload levels 0 and 1 into dense smem grids. ----
    // sm[dense(cell)] = table[hash(cell)] -- exact, collisions irrelevant.
    for (int c = threadIdx.x; c < L0_N; c += blockDim.x) {
        int iz = c % L0_SIDE;
        int r  = c / L0_SIDE;
        int iy = r % L0_SIDE;
        int ix = r / L0_SIDE;
        uint32_t h = ((uint32_t)ix ^ ((uint32_t)iy * HG_P2) ^ ((uint32_t)iz * HG_P3)) & HG_MASK;
        sm[c] = __ldg((const float2*)table + h);
    }
    for (int c = threadIdx.x; c < L1_N; c += blockDim.x) {
        int iz = c % L1_SIDE;
        int r  = c / L1_SIDE;
        int iy = r % L1_SIDE;
        int ix = r / L1_SIDE;
        uint32_t h = ((uint32_t)ix ^ ((uint32_t)iy * HG_P2) ^ ((uint32_t)iz * HG_P3)) & HG_MASK;
        sm[L0_N + c] = __ldg((const float2*)table + (h + (1u << 19)));
    }
    __syncthreads();

    int total  = n_points * 16;
    int stride = gridDim.x * blockDim.x;   // multiple of 16 -> lvl loop-invariant

    for (int t = blockIdx.x * blockDim.x + threadIdx.x; t < total; t += stride) {
        int p   = t >> 4;
        int lvl = t & 15;

        // 16 lanes share a point: broadcast loads.
        float px = x[3 * p + 0];
        float py = x[3 * p + 1];
        float pz = x[3 * p + 2];

        float res = c_res[lvl];
        // Strict IEEE float32 RN, no fma contraction (bit-exact vs reference).
        float sx = __fmul_rn(px, res);
        float sy = __fmul_rn(py, res);
        float sz = __fmul_rn(pz, res);
        float fx = floorf(sx);
        float fy = floorf(sy);
        float fz = floorf(sz);
        float wx = __fadd_rn(sx, -fx);
        float wy = __fadd_rn(sy, -fy);
        float wz = __fadd_rn(sz, -fz);

        int ix = (int)fx;
        int iy = (int)fy;
        int iz = (int)fz;

        float2 f000, f001, f010, f011, f100, f101, f110, f111;

        if (lvl >= 2) {
            // hash = ix ^ iy*P2 ^ iz*P3, masked to 19 bits.
            uint32_t hx0 = (uint32_t)ix;
            uint32_t hx1 = hx0 + 1u;
            uint32_t hy0 = (uint32_t)iy * HG_P2;
            uint32_t hy1 = hy0 + HG_P2;
            uint32_t hz0 = (uint32_t)iz * HG_P3;
            uint32_t hz1 = hz0 + HG_P3;

            const float2* tab = (const float2*)table + ((uint32_t)lvl << 19);

            f000 = __ldg(tab + ((hx0 ^ hy0 ^ hz0) & HG_MASK));
            f001 = __ldg(tab + ((hx0 ^ hy0 ^ hz1) & HG_MASK));
            f010 = __ldg(tab + ((hx0 ^ hy1 ^ hz0) & HG_MASK));
            f011 = __ldg(tab + ((hx0 ^ hy1 ^ hz1) & HG_MASK));
            f100 = __ldg(tab + ((hx1 ^ hy0 ^ hz0) & HG_MASK));
            f101 = __ldg(tab + ((hx1 ^ hy0 ^ hz1) & HG_MASK));
            f110 = __ldg(tab + ((hx1 ^ hy1 ^ hz0) & HG_MASK));
            f111 = __ldg(tab + ((hx1 ^ hy1 ^ hz1) & HG_MASK));
        } else {
            // Dense direct indexing in smem -- no hash needed.
            int side = (lvl == 0) ? L0_SIDE : L1_SIDE;
            const float2* stab = sm + ((lvl == 0) ? 0 : L0_N);
            int s2   = side * side;
            int base = (ix * side + iy) * side + iz;
            f000 = stab[base];
            f001 = stab[base + 1];
            f010 = stab[base + side];
            f011 = stab[base + side + 1];
            f100 = stab[base + s2];
            f101 = stab[base + s2 + 1];
            f110 = stab[base + s2 + side];
            f111 = stab[base + s2 + side + 1];
        }

        float wx0 = __fadd_rn(1.0f, -wx), wx1 = wx;
        float wy0 = __fadd_rn(1.0f, -wy), wy1 = wy;
        float wz0 = __fadd_rn(1.0f, -wz), wz1 = wz;

        float w000 = __fmul_rn(__fmul_rn(wx0, wy0), wz0);
        float w001 = __fmul_rn(__fmul_rn(wx0, wy0), wz1);
        float w010 = __fmul_rn(__fmul_rn(wx0, wy1), wz0);
        float w011 = __fmul_rn(__fmul_rn(wx0, wy1), wz1);
        float w100 = __fmul_rn(__fmul_rn(wx1, wy0), wz0);
        float w101 = __fmul_rn(__fmul_rn(wx1, wy0), wz1);
        float w110 = __fmul_rn(__fmul_rn(wx1, wy1), wz0);
        float w111 = __fmul_rn(__fmul_rn(wx1, wy1), wz1);

        // Reference corner order, separate RN mul + add (no FMA).
        float a0 = 0.0f, a1 = 0.0f;
        a0 = __fadd_rn(a0, __fmul_rn(f000.x, w000));  a1 = __fadd_rn(a1, __fmul_rn(f000.y, w000));
        a0 = __fadd_rn(a0, __fmul_rn(f001.x, w001));  a1 = __fadd_rn(a1, __fmul_rn(f001.y, w001));
        a0 = __fadd_rn(a0, __fmul_rn(f010.x, w010));  a1 = __fadd_rn(a1, __fmul_rn(f010.y, w010));
        a0 = __fadd_rn(a0, __fmul_rn(f011.x, w011));  a1 = __fadd_rn(a1, __fmul_rn(f011.y, w011));
        a0 = __fadd_rn(a0, __fmul_rn(f100.x, w100));  a1 = __fadd_rn(a1, __fmul_rn(f100.y, w100));
        a0 = __fadd_rn(a0, __fmul_rn(f101.x, w101));  a1 = __fadd_rn(a1, __fmul_rn(f101.y, w101));
        a0 = __fadd_rn(a0, __fmul_rn(f110.x, w110));  a1 = __fadd_rn(a1, __fmul_rn(f110.y, w110));
        a0 = __fadd_rn(a0, __fmul_rn(f111.x, w111));  a1 = __fadd_rn(a1, __fmul_rn(f111.y, w111));

        // t == p*16 + lvl -> fully coalesced 128B per point.
        out[t] = make_float2(a0, a1);
    }
}

extern "C" void kernel_launch(void* const* d_in, const int* in_sizes, int n_in,
                              void* d_out, int out_size)
{
    // Defensive input-order resolution: x (N*3) is smaller than table (T*L*F).
    const float* a = (const float*)d_in[0];
    const float* b = (const float*)d_in[1];
    int sa = in_sizes[0], sb = in_sizes[1];

    const float* x;
    const float* table;
    int x_elems;
    if (sa <= sb) { x = a; table = b; x_elems = sa; }
    else          { x = b; table = a; x_elems = sb; }

    float2* out = (float2*)d_out;
    int n_points = x_elems / 3;

    static bool attr_set = false;  // idempotent attribute set (not a work guard)
    if (!attr_set) {
        cudaFuncSetAttribute(hashgrid_kernel,
                             cudaFuncAttributeMaxDynamicSharedMemorySize, SMEM_BYTES);
        attr_set = true;
    }

    int dev = 0, sms = 148;
    cudaGetDevice(&dev);
    cudaDeviceGetAttribute(&sms, cudaDevAttrMultiProcessorCount, dev);

    // One persistent wave: grid = SM count (1 CTA/SM due to 150KB smem).
    hashgrid_kernel<<<sms, 1024, SMEM_BYTES>>>(x, table, out, n_points);
}